// round 13
// baseline (speedup 1.0000x reference)
#include <cuda_runtime.h>
#include <cuda_fp16.h>
#include <math.h>
#include <cstdint>

// Problem constants
#define B_  32
#define T_  4096
#define D_  1024
#define E_  128
#define K_  16
#define KEV_ 8
#define DK_ (D_ + E_)          // 1152
#define M_  (B_ * K_)          // 512 rows
#define KHALF (DK_ / 2)        // 576

// Output section offsets (float32, reference return order)
#define OFF_ENTRIES 0
#define OFF_VALID   (B_ * K_ * D_)                 // 524288
#define OFF_TIMES   (OFF_VALID + B_ * K_)          // 524800
#define OFF_HOLDER  (OFF_TIMES + B_ * K_)          // 525312
#define OUT_TOTAL   (OFF_HOLDER + B_ * K_ * E_)    // 590848

// Scratch
__device__ int     g_chosen[M_];
__device__ int     g_valid[M_];
__device__ __half  g_Ah[(long)M_ * DK_];
__device__ __half  g_Wh[(long)D_ * DK_];
__device__ float   g_part[2][(long)M_ * D_];       // split-k partials

// ---------------------------------------------------------------------------
// helpers
// ---------------------------------------------------------------------------
__device__ __forceinline__ uint2 pack4(float4 v) {
    __half2 H01 = __halves2half2(__float2half_rn(v.x), __float2half_rn(v.y));
    __half2 H23 = __halves2half2(__float2half_rn(v.z), __float2half_rn(v.w));
    return make_uint2(*(uint32_t*)&H01, *(uint32_t*)&H23);
}

__device__ __forceinline__ void mma_f16(float* c, const uint32_t* a,
                                        const uint32_t* b) {
    asm volatile(
        "mma.sync.aligned.m16n8k16.row.col.f32.f16.f16.f32 "
        "{%0,%1,%2,%3}, {%4,%5,%6,%7}, {%8,%9}, {%0,%1,%2,%3};"
        : "+f"(c[0]), "+f"(c[1]), "+f"(c[2]), "+f"(c[3])
        : "r"(a[0]), "r"(a[1]), "r"(a[2]), "r"(a[3]),
          "r"(b[0]), "r"(b[1]));
}

__device__ __forceinline__ void ldmx4(uint32_t* r, uint32_t addr) {
    asm volatile(
        "ldmatrix.sync.aligned.m8n8.x4.shared.b16 {%0,%1,%2,%3}, [%4];"
        : "=r"(r[0]), "=r"(r[1]), "=r"(r[2]), "=r"(r[3]) : "r"(addr));
}

__device__ __forceinline__ void cp16(uint32_t smem_dst, const void* gsrc) {
    asm volatile("cp.async.cg.shared.global [%0], [%1], 16;"
                 :: "r"(smem_dst),
                    "l"((unsigned long long)__cvta_generic_to_global(gsrc)));
}
#define CP_COMMIT() asm volatile("cp.async.commit_group;")
#define CP_WAIT(n)  asm volatile("cp.async.wait_group %0;" :: "n"(n))

__device__ __forceinline__ unsigned long long score_key(float v, int i) {
    unsigned u = __float_as_uint(v);
    u = (u & 0x80000000u) ? ~u : (u | 0x80000000u);
    return ((unsigned long long)u << 32) | (unsigned)(T_ - 1 - i);
}

// ---------------------------------------------------------------------------
// Kernel 1 (prep, heterogeneous grid):
//   blocks [0,32): choose + build A plane; blocks [32,608): pack W (fp16).
// ---------------------------------------------------------------------------
#define PACK_BLOCKS ((D_ * DK_ / 4) / 512)   // 576
#define PREP_GRID   (B_ + PACK_BLOCKS)       // 608

__global__ __launch_bounds__(512)
void prep_kernel(const float* __restrict__ scores,
                 const float* __restrict__ state,
                 const float* __restrict__ hl,
                 const float* __restrict__ W,
                 float* __restrict__ out, int out_size) {
    if (blockIdx.x >= B_) {
        long i = (long)(blockIdx.x - B_) * 512 + threadIdx.x;  // float4 idx
        *(uint2*)(g_Wh + i * 4) = pack4(((const float4*)W)[i]);
        return;
    }

    __shared__ unsigned long long wmax[16];
    __shared__ int ev[KEV_];
    __shared__ int   sc[K_];
    __shared__ float sv[K_];

    const int b = blockIdx.x;
    const int tid = threadIdx.x;
    const int lane = tid & 31, warp = tid >> 5;
    const float* sb = scores + (long)b * T_;

    unsigned long long v[8];
#pragma unroll
    for (int j = 0; j < 8; ++j)
        v[j] = score_key(sb[tid + j * 512], tid + j * 512);

#pragma unroll
    for (int round = 0; round < KEV_; ++round) {
        unsigned long long m = v[0];
#pragma unroll
        for (int j = 1; j < 8; ++j) m = (v[j] > m) ? v[j] : m;
#pragma unroll
        for (int off = 16; off > 0; off >>= 1) {
            unsigned long long o = __shfl_xor_sync(0xffffffffu, m, off);
            m = (o > m) ? o : m;
        }
        if (lane == 0) wmax[warp] = m;
        __syncthreads();
        unsigned long long bm = wmax[0];
#pragma unroll
        for (int j = 1; j < 16; ++j) bm = (wmax[j] > bm) ? wmax[j] : bm;
#pragma unroll
        for (int j = 0; j < 8; ++j) if (v[j] == bm) v[j] = 0ULL;
        if (tid == 0) ev[round] = (T_ - 1) - (int)(bm & 0xFFFFFFFFu);
        __syncthreads();
    }

    if (warp == 0) {
        if (lane < K_) { sc[lane] = 0; sv[lane] = 0.f; }
        __syncwarp();
        int myv;
        if (lane < KEV_)            myv = ev[lane];
        else if (lane < KEV_ + K_)  myv = (int)((float)(lane - KEV_) *
                                                ((float)(T_ - 1) / (K_ - 1)));
        else                        myv = 0x7FFFFFFF;
        int firstocc = (lane < KEV_ + K_) ? 1 : 0;
#pragma unroll
        for (int j = 0; j < KEV_ + K_; ++j) {
            int vj = __shfl_sync(0xffffffffu, myv, j);
            if (j < lane && vj == myv) firstocc = 0;
        }
        unsigned fmask = __ballot_sync(0xffffffffu, firstocc);
        int rank = 0;
#pragma unroll
        for (int j = 0; j < KEV_ + K_; ++j) {
            int vj = __shfl_sync(0xffffffffu, myv, j);
            if (((fmask >> j) & 1u) && vj < myv) ++rank;
        }
        const int n = __popc(fmask);
        const int nv = n < K_ ? n : K_;
        if (firstocc && rank < K_) {
            sc[rank] = myv;
            sv[rank] = (rank < nv) ? 1.f : 0.f;
        }
        __syncwarp();
        if (lane < K_) {
            g_chosen[b * K_ + lane] = sc[lane];
            g_valid[b * K_ + lane]  = (int)sv[lane];
            if (out_size >= OUT_TOTAL) {
                out[OFF_VALID + b * K_ + lane] = sv[lane];
                out[OFF_TIMES + b * K_ + lane] = (float)sc[lane] * sv[lane];
            }
        }
    }
    __syncthreads();

    {
        const int rr = warp;
        const int row = b * K_ + rr;
        const int idx = sc[rr];
        const float vf = sv[rr];

        const float4 hv =
            ((const float4*)(hl + ((long)b * T_ + idx) * E_))[lane];
        if (out_size >= OUT_TOTAL) {
            float4 ho;
            ho.x = hv.x * vf; ho.y = hv.y * vf;
            ho.z = hv.z * vf; ho.w = hv.w * vf;
            ((float4*)(out + OFF_HOLDER + (long)row * E_))[lane] = ho;
        }
        float mx = fmaxf(fmaxf(hv.x, hv.y), fmaxf(hv.z, hv.w));
#pragma unroll
        for (int off = 16; off > 0; off >>= 1)
            mx = fmaxf(mx, __shfl_xor_sync(0xffffffffu, mx, off));
        float4 ex;
        ex.x = expf(hv.x - mx); ex.y = expf(hv.y - mx);
        ex.z = expf(hv.z - mx); ex.w = expf(hv.w - mx);
        float s = ex.x + ex.y + ex.z + ex.w;
#pragma unroll
        for (int off = 16; off > 0; off >>= 1)
            s += __shfl_xor_sync(0xffffffffu, s, off);
        float inv = 1.0f / s;
        float4 p;
        p.x = ex.x * inv; p.y = ex.y * inv; p.z = ex.z * inv; p.w = ex.w * inv;

        __half* ah = g_Ah + (long)row * DK_;
        *(uint2*)(ah + D_ + lane * 4) = pack4(p);

        const float4* src = (const float4*)(state + ((long)b * T_ + idx) * D_);
#pragma unroll
        for (int t = 0; t < 8; ++t) {
            int q = lane + t * 32;
            *(uint2*)(ah + q * 4) = pack4(src[q]);
        }
    }
}

// ---------------------------------------------------------------------------
// Kernel 2: HMMA fp16 GEMM, split-k=2 across blockIdx.z.
// Tile 32(M)x64(N), 256 threads = 8 warps (2m x 4n, warp tile 16x16).
// GBK=64, 9 stages per half-k, 3-stage cp.async, 41.5 KB smem -> ~3.5 CTA/SM.
// In-stage register double-buffering of ldmatrix fragments.
// Writes fp32 partials to g_part[kz].
// ---------------------------------------------------------------------------
#define GBM 32
#define GBN 64
#define GBK 64
#define NSTAGE (KHALF / GBK)  // 9
#define STAGES 3
#define PADK 72               // 144B rows, conflict-free
#define A_PLANE (32 * PADK)               // 2304 elems
#define B_PLANE (64 * PADK)               // 4608 elems
#define STAGE_ELEMS (A_PLANE + B_PLANE)   // 6912 elems = 13824 B
#define OFF_AH 0
#define OFF_BH A_PLANE
#define SMEM_BYTES (STAGES * STAGE_ELEMS * 2)     // 41472

__global__ __launch_bounds__(256)
void gemm_hmma_kernel() {
    extern __shared__ __half smem[];
    const uint32_t sbase = (uint32_t)__cvta_generic_to_shared(smem);

    const int tid = threadIdx.x;
    const int lane = tid & 31;
    const int warp = tid >> 5;              // 0..7
    const int warp_m = (warp & 1) * 16;     // 0 or 16
    const int warp_n = (warp >> 1) * 16;    // 0,16,32,48
    const int bm = blockIdx.y * GBM;
    const int bn = blockIdx.x * GBN;
    const int kz = blockIdx.z;              // 0 or 1
    const long kbase = (long)kz * KHALF;

    const int lrow = tid >> 3;              // 0..31
    const int lcq  = tid & 7;               // 0..7

    auto load_stage = [&](int st, int buf) {
        const long k0 = kbase + (long)st * GBK;
        const uint32_t sb0 = sbase + (uint32_t)(buf * STAGE_ELEMS) * 2;
        {
            const long aoff = (long)(bm + lrow) * DK_ + k0 + lcq * 8;
            const uint32_t soff = (uint32_t)(lrow * PADK + lcq * 8);
            cp16(sb0 + (OFF_AH + soff) * 2, g_Ah + aoff);
        }
#pragma unroll
        for (int h = 0; h < 2; ++h) {
            const int row = lrow + h * 32;
            const long boff = (long)(bn + row) * DK_ + k0 + lcq * 8;
            const uint32_t soff = (uint32_t)(row * PADK + lcq * 8);
            cp16(sb0 + (OFF_BH + soff) * 2, g_Wh + boff);
        }
        CP_COMMIT();
    };

    // ldmatrix lane mapping
    const int r8 = lane & 7;
    const int quad = lane >> 3;
    const int lm = (quad & 1) * 8 + r8;
    const int lk = (quad >> 1) * 8;

    float acc[2][4];
#pragma unroll
    for (int j = 0; j < 2; ++j)
#pragma unroll
        for (int q = 0; q < 4; ++q) acc[j][q] = 0.f;

    load_stage(0, 0);
    load_stage(1, 1);

    for (int st = 0; st < NSTAGE; ++st) {
        if (st + 1 < NSTAGE) { CP_WAIT(1); } else { CP_WAIT(0); }
        __syncthreads();
        if (st + 2 < NSTAGE) load_stage(st + 2, (st + 2) % 3);

        const uint32_t sb0 = sbase + (uint32_t)((st % 3) * STAGE_ELEMS) * 2;
        const uint32_t abase = sb0 + OFF_AH * 2 +
                               (uint32_t)((warp_m + lm) * PADK + lk) * 2;
        const uint32_t bbase = sb0 + OFF_BH * 2 +
                               (uint32_t)((warp_n + lm) * PADK + lk) * 2;

        // register double-buffered k16 steps (4 per stage)
        uint32_t ah[2][4], bh[2][4];
        ldmx4(ah[0], abase);
        ldmx4(bh[0], bbase);
#pragma unroll
        for (int ks = 0; ks < 4; ++ks) {
            const int cur = ks & 1, nxt = cur ^ 1;
            if (ks < 3) {
                const uint32_t koff = (uint32_t)((ks + 1) * 16) * 2;
                ldmx4(ah[nxt], abase + koff);
                ldmx4(bh[nxt], bbase + koff);
            }
            uint32_t b0[2] = {bh[cur][0], bh[cur][2]};
            uint32_t b1[2] = {bh[cur][1], bh[cur][3]};
            mma_f16(acc[0], ah[cur], b0);
            mma_f16(acc[1], ah[cur], b1);
        }
    }

    // ---- write fp32 partials ----
    const int r = lane >> 2;
    const int kq = (lane & 3) * 2;
    float* pp = g_part[kz];
#pragma unroll
    for (int half = 0; half < 2; ++half) {
        const int m = bm + warp_m + r + half * 8;
        float* op = pp + (long)m * D_;
#pragma unroll
        for (int nt = 0; nt < 2; ++nt) {
            const int n0 = bn + warp_n + nt * 8 + kq;
            float2 o;
            o.x = acc[nt][half * 2 + 0];
            o.y = acc[nt][half * 2 + 1];
            *(float2*)(op + n0) = o;
        }
    }
}

// ---------------------------------------------------------------------------
// Kernel 3: reduce + epilogue. One block per m row (512 blocks x 256 thr).
//   out[m,n] = (p0 + p1 + bias[n] + time_table[clip(chosen_m)][n]) * valid_m
// ---------------------------------------------------------------------------
__global__ __launch_bounds__(256)
void reduce_kernel(const float* __restrict__ bias,
                   const float* __restrict__ time_table,
                   float* __restrict__ out) {
    const int m = blockIdx.x;
    const int t = threadIdx.x;            // 256 threads x float4 = 1024
    int tt = g_chosen[m];
    tt = tt < 0 ? 0 : (tt > 511 ? 511 : tt);
    const float vf = (float)g_valid[m];

    const float4 p0 = ((const float4*)(g_part[0] + (long)m * D_))[t];
    const float4 p1 = ((const float4*)(g_part[1] + (long)m * D_))[t];
    const float4 bi = ((const float4*)bias)[t];
    const float4 te = ((const float4*)(time_table + (long)tt * D_))[t];
    float4 o;
    o.x = (p0.x + p1.x + bi.x + te.x) * vf;
    o.y = (p0.y + p1.y + bi.y + te.y) * vf;
    o.z = (p0.z + p1.z + bi.z + te.z) * vf;
    o.w = (p0.w + p1.w + bi.w + te.w) * vf;
    ((float4*)(out + OFF_ENTRIES + (long)m * D_))[t] = o;
}

// ---------------------------------------------------------------------------
// Launch. Inputs: state_seq, holder_logits, event_scores, W, b, time_table
// ---------------------------------------------------------------------------
extern "C" void kernel_launch(void* const* d_in, const int* in_sizes, int n_in,
                              void* d_out, int out_size) {
    const float* state  = (const float*)d_in[0];
    const float* hl     = (const float*)d_in[1];
    const float* scores = (const float*)d_in[2];
    const float* W      = (const float*)d_in[3];
    const float* bias   = (const float*)d_in[4];
    const float* ttab   = (const float*)d_in[5];
    float* out = (float*)d_out;

    cudaFuncSetAttribute(gemm_hmma_kernel,
                         cudaFuncAttributeMaxDynamicSharedMemorySize,
                         SMEM_BYTES);

    prep_kernel<<<PREP_GRID, 512>>>(scores, state, hl, W, out, out_size);
    dim3 grid(D_ / GBN, M_ / GBM, 2);   // (16, 16, 2) = 512 CTAs
    gemm_hmma_kernel<<<grid, 256, SMEM_BYTES>>>();
    reduce_kernel<<<M_, 256>>>(bias, ttab, out);
}

// round 14
// speedup vs baseline: 1.0986x; 1.0986x over previous
#include <cuda_runtime.h>
#include <cuda_fp16.h>
#include <math.h>
#include <cstdint>

// Problem constants
#define B_  32
#define T_  4096
#define D_  1024
#define E_  128
#define K_  16
#define KEV_ 8
#define DK_ (D_ + E_)          // 1152
#define M_  (B_ * K_)          // 512 rows

// Output section offsets (float32, reference return order)
#define OFF_ENTRIES 0
#define OFF_VALID   (B_ * K_ * D_)                 // 524288
#define OFF_TIMES   (OFF_VALID + B_ * K_)          // 524800
#define OFF_HOLDER  (OFF_TIMES + B_ * K_)          // 525312
#define OUT_TOTAL   (OFF_HOLDER + B_ * K_ * E_)    // 590848

// Scratch: single fp16 planes for A (gathered raw) and W.
__device__ int     g_chosen[M_];
__device__ int     g_valid[M_];
__device__ __half  g_Ah[(long)M_ * DK_];
__device__ __half  g_Wh[(long)D_ * DK_];

// ---------------------------------------------------------------------------
// helpers
// ---------------------------------------------------------------------------
__device__ __forceinline__ uint2 pack4(float4 v) {
    __half2 H01 = __halves2half2(__float2half_rn(v.x), __float2half_rn(v.y));
    __half2 H23 = __halves2half2(__float2half_rn(v.z), __float2half_rn(v.w));
    return make_uint2(*(uint32_t*)&H01, *(uint32_t*)&H23);
}

__device__ __forceinline__ void mma_f16(float* c, const uint32_t* a,
                                        const uint32_t* b) {
    asm volatile(
        "mma.sync.aligned.m16n8k16.row.col.f32.f16.f16.f32 "
        "{%0,%1,%2,%3}, {%4,%5,%6,%7}, {%8,%9}, {%0,%1,%2,%3};"
        : "+f"(c[0]), "+f"(c[1]), "+f"(c[2]), "+f"(c[3])
        : "r"(a[0]), "r"(a[1]), "r"(a[2]), "r"(a[3]),
          "r"(b[0]), "r"(b[1]));
}

__device__ __forceinline__ void ldmx4(uint32_t* r, uint32_t addr) {
    asm volatile(
        "ldmatrix.sync.aligned.m8n8.x4.shared.b16 {%0,%1,%2,%3}, [%4];"
        : "=r"(r[0]), "=r"(r[1]), "=r"(r[2]), "=r"(r[3]) : "r"(addr));
}

__device__ __forceinline__ void cp16(uint32_t smem_dst, const void* gsrc) {
    asm volatile("cp.async.cg.shared.global [%0], [%1], 16;"
                 :: "r"(smem_dst),
                    "l"((unsigned long long)__cvta_generic_to_global(gsrc)));
}
#define CP_COMMIT() asm volatile("cp.async.commit_group;")
#define CP_WAIT(n)  asm volatile("cp.async.wait_group %0;" :: "n"(n))

__device__ __forceinline__ unsigned long long score_key(float v, int i) {
    unsigned u = __float_as_uint(v);
    u = (u & 0x80000000u) ? ~u : (u | 0x80000000u);
    return ((unsigned long long)u << 32) | (unsigned)(T_ - 1 - i);
}

// ---------------------------------------------------------------------------
// Kernel 1 (prep, heterogeneous grid):
//   blocks [0,32): choose + build A plane
//   blocks [32, 32+144): pack W -> fp16, 4 float4 per thread (MLP=4)
// ---------------------------------------------------------------------------
#define PACK_BLOCKS 144                      // 144 * 512 * 4 = 294912 float4
#define PREP_GRID   (B_ + PACK_BLOCKS)       // 176

__global__ __launch_bounds__(512)
void prep_kernel(const float* __restrict__ scores,
                 const float* __restrict__ state,
                 const float* __restrict__ hl,
                 const float* __restrict__ W,
                 float* __restrict__ out, int out_size) {
    if (blockIdx.x >= B_) {
        const long base = (long)(blockIdx.x - B_) * 2048 + threadIdx.x;
        const float4* Wv = (const float4*)W;
        float4 v0 = Wv[base];
        float4 v1 = Wv[base + 512];
        float4 v2 = Wv[base + 1024];
        float4 v3 = Wv[base + 1536];
        *(uint2*)(g_Wh + (base)        * 4) = pack4(v0);
        *(uint2*)(g_Wh + (base + 512)  * 4) = pack4(v1);
        *(uint2*)(g_Wh + (base + 1024) * 4) = pack4(v2);
        *(uint2*)(g_Wh + (base + 1536) * 4) = pack4(v3);
        return;
    }

    __shared__ unsigned long long wmax[16];
    __shared__ int ev[KEV_];
    __shared__ int   sc[K_];
    __shared__ float sv[K_];

    const int b = blockIdx.x;
    const int tid = threadIdx.x;
    const int lane = tid & 31, warp = tid >> 5;
    const float* sb = scores + (long)b * T_;

    unsigned long long v[8];
#pragma unroll
    for (int j = 0; j < 8; ++j)
        v[j] = score_key(sb[tid + j * 512], tid + j * 512);

#pragma unroll
    for (int round = 0; round < KEV_; ++round) {
        unsigned long long m = v[0];
#pragma unroll
        for (int j = 1; j < 8; ++j) m = (v[j] > m) ? v[j] : m;
#pragma unroll
        for (int off = 16; off > 0; off >>= 1) {
            unsigned long long o = __shfl_xor_sync(0xffffffffu, m, off);
            m = (o > m) ? o : m;
        }
        if (lane == 0) wmax[warp] = m;
        __syncthreads();
        unsigned long long bm = wmax[0];
#pragma unroll
        for (int j = 1; j < 16; ++j) bm = (wmax[j] > bm) ? wmax[j] : bm;
#pragma unroll
        for (int j = 0; j < 8; ++j) if (v[j] == bm) v[j] = 0ULL;
        if (tid == 0) ev[round] = (T_ - 1) - (int)(bm & 0xFFFFFFFFu);
        __syncthreads();
    }

    if (warp == 0) {
        if (lane < K_) { sc[lane] = 0; sv[lane] = 0.f; }
        __syncwarp();
        int myv;
        if (lane < KEV_)            myv = ev[lane];
        else if (lane < KEV_ + K_)  myv = (int)((float)(lane - KEV_) *
                                                ((float)(T_ - 1) / (K_ - 1)));
        else                        myv = 0x7FFFFFFF;
        int firstocc = (lane < KEV_ + K_) ? 1 : 0;
#pragma unroll
        for (int j = 0; j < KEV_ + K_; ++j) {
            int vj = __shfl_sync(0xffffffffu, myv, j);
            if (j < lane && vj == myv) firstocc = 0;
        }
        unsigned fmask = __ballot_sync(0xffffffffu, firstocc);
        int rank = 0;
#pragma unroll
        for (int j = 0; j < KEV_ + K_; ++j) {
            int vj = __shfl_sync(0xffffffffu, myv, j);
            if (((fmask >> j) & 1u) && vj < myv) ++rank;
        }
        const int n = __popc(fmask);
        const int nv = n < K_ ? n : K_;
        if (firstocc && rank < K_) {
            sc[rank] = myv;
            sv[rank] = (rank < nv) ? 1.f : 0.f;
        }
        __syncwarp();
        if (lane < K_) {
            g_chosen[b * K_ + lane] = sc[lane];
            g_valid[b * K_ + lane]  = (int)sv[lane];
            if (out_size >= OUT_TOTAL) {
                out[OFF_VALID + b * K_ + lane] = sv[lane];
                out[OFF_TIMES + b * K_ + lane] = (float)sc[lane] * sv[lane];
            }
        }
    }
    __syncthreads();

    {
        const int rr = warp;
        const int row = b * K_ + rr;
        const int idx = sc[rr];
        const float vf = sv[rr];

        const float4 hv =
            ((const float4*)(hl + ((long)b * T_ + idx) * E_))[lane];
        if (out_size >= OUT_TOTAL) {
            float4 ho;
            ho.x = hv.x * vf; ho.y = hv.y * vf;
            ho.z = hv.z * vf; ho.w = hv.w * vf;
            ((float4*)(out + OFF_HOLDER + (long)row * E_))[lane] = ho;
        }
        float mx = fmaxf(fmaxf(hv.x, hv.y), fmaxf(hv.z, hv.w));
#pragma unroll
        for (int off = 16; off > 0; off >>= 1)
            mx = fmaxf(mx, __shfl_xor_sync(0xffffffffu, mx, off));
        float4 ex;
        ex.x = expf(hv.x - mx); ex.y = expf(hv.y - mx);
        ex.z = expf(hv.z - mx); ex.w = expf(hv.w - mx);
        float s = ex.x + ex.y + ex.z + ex.w;
#pragma unroll
        for (int off = 16; off > 0; off >>= 1)
            s += __shfl_xor_sync(0xffffffffu, s, off);
        float inv = 1.0f / s;
        float4 p;
        p.x = ex.x * inv; p.y = ex.y * inv; p.z = ex.z * inv; p.w = ex.w * inv;

        __half* ah = g_Ah + (long)row * DK_;
        *(uint2*)(ah + D_ + lane * 4) = pack4(p);

        const float4* src = (const float4*)(state + ((long)b * T_ + idx) * D_);
#pragma unroll
        for (int t = 0; t < 8; ++t) {
            int q = lane + t * 32;
            *(uint2*)(ah + q * 4) = pack4(src[q]);
        }
    }
}

// ---------------------------------------------------------------------------
// Kernel 2: HMMA fp16 single-pass GEMM (R11 config — measured 13.3us).
//   C[512,1024] = A_f16[512,1152] @ W_f16[1024,1152]^T
// CTA tile 32(M)x64(N), 256 threads = 8 warps (2m x 4n, warp tile 16x16).
// GBK=64, 4-stage cp.async; 2 smem planes/stage (A, B). 55KB smem.
// ---------------------------------------------------------------------------
#define GBM 32
#define GBN 64
#define GBK 64
#define NSTAGE (DK_ / GBK)    // 18
#define STAGES 4
#define PADK 72               // 144B rows, ldmatrix conflict-free
#define A_PLANE (32 * PADK)               // 2304 elems
#define B_PLANE (64 * PADK)               // 4608 elems
#define STAGE_ELEMS (A_PLANE + B_PLANE)   // 6912 elems = 13824 B
#define OFF_AH 0
#define OFF_BH A_PLANE
#define SMEM_BYTES (STAGES * STAGE_ELEMS * 2)     // 55296

__global__ __launch_bounds__(256)
void gemm_hmma_kernel(const float* __restrict__ bias,
                      const float* __restrict__ time_table,
                      float* __restrict__ out) {
    extern __shared__ __half smem[];
    const uint32_t sbase = (uint32_t)__cvta_generic_to_shared(smem);

    const int tid = threadIdx.x;
    const int lane = tid & 31;
    const int warp = tid >> 5;              // 0..7
    const int warp_m = (warp & 1) * 16;     // 0 or 16
    const int warp_n = (warp >> 1) * 16;    // 0,16,32,48
    const int bm = blockIdx.y * GBM;
    const int bn = blockIdx.x * GBN;

    const int lrow = tid >> 3;              // 0..31
    const int lcq  = tid & 7;               // 0..7 (16B chunks of 128B)

    auto load_stage = [&](int st, int buf) {
        const long k0 = (long)st * GBK;
        const uint32_t sb0 = sbase + (uint32_t)(buf * STAGE_ELEMS) * 2;
        {
            const long aoff = (long)(bm + lrow) * DK_ + k0 + lcq * 8;
            const uint32_t soff = (uint32_t)(lrow * PADK + lcq * 8);
            cp16(sb0 + (OFF_AH + soff) * 2, g_Ah + aoff);
        }
#pragma unroll
        for (int h = 0; h < 2; ++h) {
            const int row = lrow + h * 32;
            const long boff = (long)(bn + row) * DK_ + k0 + lcq * 8;
            const uint32_t soff = (uint32_t)(row * PADK + lcq * 8);
            cp16(sb0 + (OFF_BH + soff) * 2, g_Wh + boff);
        }
        CP_COMMIT();
    };

    // ldmatrix lane mapping
    const int r8 = lane & 7;
    const int quad = lane >> 3;
    const int lm = (quad & 1) * 8 + r8;
    const int lk = (quad >> 1) * 8;

    float acc[2][4];
#pragma unroll
    for (int j = 0; j < 2; ++j)
#pragma unroll
        for (int q = 0; q < 4; ++q) acc[j][q] = 0.f;

    load_stage(0, 0);
    load_stage(1, 1);
    load_stage(2, 2);

    for (int st = 0; st < NSTAGE; ++st) {
        if (st < NSTAGE - 2)       { CP_WAIT(2); }
        else if (st == NSTAGE - 2) { CP_WAIT(1); }
        else                       { CP_WAIT(0); }
        __syncthreads();
        if (st + 3 < NSTAGE) load_stage(st + 3, (st + 3) & 3);

        const uint32_t sb0 = sbase + (uint32_t)((st & 3) * STAGE_ELEMS) * 2;
        const uint32_t abase = sb0 + OFF_AH * 2;
        const uint32_t bbase = sb0 + OFF_BH * 2;

#pragma unroll
        for (int ks = 0; ks < 4; ++ks) {
            const int kb = ks * 16;
            uint32_t ah[4], bh[4];
            const uint32_t ra = (uint32_t)((warp_m + lm) * PADK + kb + lk) * 2;
            const uint32_t rb = (uint32_t)((warp_n + lm) * PADK + kb + lk) * 2;
            ldmx4(ah, abase + ra);
            ldmx4(bh, bbase + rb);

            uint32_t bh0[2] = {bh[0], bh[2]}, bh1[2] = {bh[1], bh[3]};

            mma_f16(acc[0], ah, bh0);
            mma_f16(acc[1], ah, bh1);
        }
    }

    // ---- epilogue: + bias + time_table[clip(chosen,0,511)], * valid ----
    const int r = lane >> 2;
    const int kq = (lane & 3) * 2;
#pragma unroll
    for (int half = 0; half < 2; ++half) {
        const int m = bm + warp_m + r + half * 8;
        int tt = g_chosen[m];
        tt = tt < 0 ? 0 : (tt > 511 ? 511 : tt);
        const float vf = (float)g_valid[m];
        const float* te = time_table + (long)tt * D_;
        float* op = out + OFF_ENTRIES + (long)m * D_;
#pragma unroll
        for (int nt = 0; nt < 2; ++nt) {
            const int n0 = bn + warp_n + nt * 8 + kq;
            const float c0 = acc[nt][half * 2 + 0];
            const float c1 = acc[nt][half * 2 + 1];
            float2 o;
            o.x = (c0 + bias[n0]     + te[n0])     * vf;
            o.y = (c1 + bias[n0 + 1] + te[n0 + 1]) * vf;
            *(float2*)(op + n0) = o;
        }
    }
}

// ---------------------------------------------------------------------------
// Launch. Inputs: state_seq, holder_logits, event_scores, W, b, time_table
// ---------------------------------------------------------------------------
extern "C" void kernel_launch(void* const* d_in, const int* in_sizes, int n_in,
                              void* d_out, int out_size) {
    const float* state  = (const float*)d_in[0];
    const float* hl     = (const float*)d_in[1];
    const float* scores = (const float*)d_in[2];
    const float* W      = (const float*)d_in[3];
    const float* bias   = (const float*)d_in[4];
    const float* ttab   = (const float*)d_in[5];
    float* out = (float*)d_out;

    cudaFuncSetAttribute(gemm_hmma_kernel,
                         cudaFuncAttributeMaxDynamicSharedMemorySize,
                         SMEM_BYTES);

    prep_kernel<<<PREP_GRID, 512>>>(scores, state, hl, W, out, out_size);
    dim3 grid(D_ / GBN, M_ / GBM);   // (16, 16) = 256 CTAs
    gemm_hmma_kernel<<<grid, 256, SMEM_BYTES>>>(bias, ttab, out);
}

// round 15
// speedup vs baseline: 1.2076x; 1.0992x over previous
#include <cuda_runtime.h>
#include <cuda_fp16.h>
#include <math.h>
#include <cstdint>

// Problem constants
#define B_  32
#define T_  4096
#define D_  1024
#define E_  128
#define K_  16
#define KEV_ 8
#define DK_ (D_ + E_)          // 1152
#define M_  (B_ * K_)          // 512 rows

// Output section offsets (float32, reference return order)
#define OFF_ENTRIES 0
#define OFF_VALID   (B_ * K_ * D_)                 // 524288
#define OFF_TIMES   (OFF_VALID + B_ * K_)          // 524800
#define OFF_HOLDER  (OFF_TIMES + B_ * K_)          // 525312
#define OUT_TOTAL   (OFF_HOLDER + B_ * K_ * E_)    // 590848

// Scratch: single fp16 planes for A (gathered raw) and W.
__device__ int     g_chosen[M_];
__device__ int     g_valid[M_];
__device__ __half  g_Ah[(long)M_ * DK_];
__device__ __half  g_Wh[(long)D_ * DK_];

// ---------------------------------------------------------------------------
// helpers
// ---------------------------------------------------------------------------
__device__ __forceinline__ uint2 pack4(float4 v) {
    __half2 H01 = __halves2half2(__float2half_rn(v.x), __float2half_rn(v.y));
    __half2 H23 = __halves2half2(__float2half_rn(v.z), __float2half_rn(v.w));
    return make_uint2(*(uint32_t*)&H01, *(uint32_t*)&H23);
}

__device__ __forceinline__ void mma_f16(float* c, const uint32_t* a,
                                        const uint32_t* b) {
    asm volatile(
        "mma.sync.aligned.m16n8k16.row.col.f32.f16.f16.f32 "
        "{%0,%1,%2,%3}, {%4,%5,%6,%7}, {%8,%9}, {%0,%1,%2,%3};"
        : "+f"(c[0]), "+f"(c[1]), "+f"(c[2]), "+f"(c[3])
        : "r"(a[0]), "r"(a[1]), "r"(a[2]), "r"(a[3]),
          "r"(b[0]), "r"(b[1]));
}

__device__ __forceinline__ void ldmx4(uint32_t* r, uint32_t addr) {
    asm volatile(
        "ldmatrix.sync.aligned.m8n8.x4.shared.b16 {%0,%1,%2,%3}, [%4];"
        : "=r"(r[0]), "=r"(r[1]), "=r"(r[2]), "=r"(r[3]) : "r"(addr));
}

__device__ __forceinline__ void cp16(uint32_t smem_dst, const void* gsrc) {
    asm volatile("cp.async.cg.shared.global [%0], [%1], 16;"
                 :: "r"(smem_dst),
                    "l"((unsigned long long)__cvta_generic_to_global(gsrc)));
}
#define CP_COMMIT() asm volatile("cp.async.commit_group;")
#define CP_WAIT(n)  asm volatile("cp.async.wait_group %0;" :: "n"(n))

__device__ __forceinline__ unsigned long long score_key(float v, int i) {
    unsigned u = __float_as_uint(v);
    u = (u & 0x80000000u) ? ~u : (u | 0x80000000u);
    return ((unsigned long long)u << 32) | (unsigned)(T_ - 1 - i);
}

__device__ __forceinline__ unsigned long long wmax64(unsigned long long m) {
#pragma unroll
    for (int off = 16; off > 0; off >>= 1) {
        unsigned long long o = __shfl_xor_sync(0xffffffffu, m, off);
        m = (o > m) ? o : m;
    }
    return m;
}

// ---------------------------------------------------------------------------
// Kernel 1 (prep, heterogeneous grid):
//   blocks [0,32): choose (single-barrier merge topk) + build A plane
//   blocks [32, 32+144): pack W -> fp16, 4 float4 per thread (MLP=4)
// ---------------------------------------------------------------------------
#define PACK_BLOCKS 144                      // 144 * 512 * 4 = 294912 float4
#define PREP_GRID   (B_ + PACK_BLOCKS)       // 176

#define SWAPD(i, j) { if (a[i] < a[j]) { unsigned long long t = a[i]; a[i] = a[j]; a[j] = t; } }

__global__ __launch_bounds__(512)
void prep_kernel(const float* __restrict__ scores,
                 const float* __restrict__ state,
                 const float* __restrict__ hl,
                 const float* __restrict__ W,
                 float* __restrict__ out, int out_size) {
    if (blockIdx.x >= B_) {
        const long base = (long)(blockIdx.x - B_) * 2048 + threadIdx.x;
        const float4* Wv = (const float4*)W;
        float4 v0 = Wv[base];
        float4 v1 = Wv[base + 512];
        float4 v2 = Wv[base + 1024];
        float4 v3 = Wv[base + 1536];
        *(uint2*)(g_Wh + (base)        * 4) = pack4(v0);
        *(uint2*)(g_Wh + (base + 512)  * 4) = pack4(v1);
        *(uint2*)(g_Wh + (base + 1024) * 4) = pack4(v2);
        *(uint2*)(g_Wh + (base + 1536) * 4) = pack4(v3);
        return;
    }

    __shared__ unsigned long long wtop[16][KEV_];
    __shared__ int   sc[K_];
    __shared__ float sv[K_];

    const int b = blockIdx.x;
    const int tid = threadIdx.x;           // 0..511
    const int lane = tid & 31, warp = tid >> 5;   // 16 warps
    const float* sb = scores + (long)b * T_;

    // ---- per-thread 8 keys, sorted descending via static network ----
    unsigned long long a[8];
#pragma unroll
    for (int j = 0; j < 8; ++j)
        a[j] = score_key(sb[tid + j * 512], tid + j * 512);
    // optimal 8-element sorting network (19 comparators), descending
    SWAPD(0,1) SWAPD(2,3) SWAPD(4,5) SWAPD(6,7)
    SWAPD(0,2) SWAPD(1,3) SWAPD(4,6) SWAPD(5,7)
    SWAPD(1,2) SWAPD(5,6) SWAPD(0,4) SWAPD(3,7)
    SWAPD(1,5) SWAPD(2,6)
    SWAPD(1,4) SWAPD(3,6)
    SWAPD(2,4) SWAPD(3,5)
    SWAPD(3,4)

    // ---- warp merge: 8 rounds of head-max + static predicated shift ----
    unsigned long long w[8];
#pragma unroll
    for (int r = 0; r < KEV_; ++r) {
        unsigned long long m = wmax64(a[0]);
        if (a[0] == m) {                // keys unique -> exactly one lane
            a[0]=a[1]; a[1]=a[2]; a[2]=a[3]; a[3]=a[4];
            a[4]=a[5]; a[5]=a[6]; a[6]=a[7]; a[7]=0ULL;
        }
        w[r] = m;
    }
    if (lane == 0) {
#pragma unroll
        for (int r = 0; r < KEV_; ++r) wtop[warp][r] = w[r];
    }
    __syncthreads();

    // ---- warp 0: merge 16 sorted lists, then dedup/rank with grid ----
    if (warp == 0) {
        unsigned long long l[8];
#pragma unroll
        for (int r = 0; r < KEV_; ++r)
            l[r] = (lane < 16) ? wtop[lane][r] : 0ULL;

        int myv = 0x7FFFFFFF;
#pragma unroll
        for (int r = 0; r < KEV_; ++r) {
            unsigned long long m = wmax64(l[0]);
            if (lane < 16 && l[0] == m) {
                l[0]=l[1]; l[1]=l[2]; l[2]=l[3]; l[3]=l[4];
                l[4]=l[5]; l[5]=l[6]; l[6]=l[7]; l[7]=0ULL;
            }
            if (lane == r) myv = (T_ - 1) - (int)(m & 0xFFFFFFFFu);
        }
        // lanes 8..23: uniform grid; others sentinel
        if (lane >= KEV_ && lane < KEV_ + K_)
            myv = (int)((float)(lane - KEV_) * ((float)(T_ - 1) / (K_ - 1)));

        if (lane < K_) { sc[lane] = 0; sv[lane] = 0.f; }
        __syncwarp();
        int firstocc = (lane < KEV_ + K_) ? 1 : 0;
#pragma unroll
        for (int j = 0; j < KEV_ + K_; ++j) {
            int vj = __shfl_sync(0xffffffffu, myv, j);
            if (j < lane && vj == myv) firstocc = 0;
        }
        unsigned fmask = __ballot_sync(0xffffffffu, firstocc);
        int rank = 0;
#pragma unroll
        for (int j = 0; j < KEV_ + K_; ++j) {
            int vj = __shfl_sync(0xffffffffu, myv, j);
            if (((fmask >> j) & 1u) && vj < myv) ++rank;
        }
        const int n = __popc(fmask);
        const int nv = n < K_ ? n : K_;
        if (firstocc && rank < K_) {
            sc[rank] = myv;
            sv[rank] = (rank < nv) ? 1.f : 0.f;
        }
        __syncwarp();
        if (lane < K_) {
            g_chosen[b * K_ + lane] = sc[lane];
            g_valid[b * K_ + lane]  = (int)sv[lane];
            if (out_size >= OUT_TOTAL) {
                out[OFF_VALID + b * K_ + lane] = sv[lane];
                out[OFF_TIMES + b * K_ + lane] = (float)sc[lane] * sv[lane];
            }
        }
    }
    __syncthreads();

    // ---- warp-per-row: gather + softmax + fp16 A plane + holder ----
    {
        const int rr = warp;
        const int row = b * K_ + rr;
        const int idx = sc[rr];
        const float vf = sv[rr];

        const float4 hv =
            ((const float4*)(hl + ((long)b * T_ + idx) * E_))[lane];
        if (out_size >= OUT_TOTAL) {
            float4 ho;
            ho.x = hv.x * vf; ho.y = hv.y * vf;
            ho.z = hv.z * vf; ho.w = hv.w * vf;
            ((float4*)(out + OFF_HOLDER + (long)row * E_))[lane] = ho;
        }
        float mx = fmaxf(fmaxf(hv.x, hv.y), fmaxf(hv.z, hv.w));
#pragma unroll
        for (int off = 16; off > 0; off >>= 1)
            mx = fmaxf(mx, __shfl_xor_sync(0xffffffffu, mx, off));
        float4 ex;
        ex.x = expf(hv.x - mx); ex.y = expf(hv.y - mx);
        ex.z = expf(hv.z - mx); ex.w = expf(hv.w - mx);
        float s = ex.x + ex.y + ex.z + ex.w;
#pragma unroll
        for (int off = 16; off > 0; off >>= 1)
            s += __shfl_xor_sync(0xffffffffu, s, off);
        float inv = 1.0f / s;
        float4 p;
        p.x = ex.x * inv; p.y = ex.y * inv; p.z = ex.z * inv; p.w = ex.w * inv;

        __half* ah = g_Ah + (long)row * DK_;
        *(uint2*)(ah + D_ + lane * 4) = pack4(p);

        const float4* src = (const float4*)(state + ((long)b * T_ + idx) * D_);
#pragma unroll
        for (int t = 0; t < 8; ++t) {
            int q = lane + t * 32;
            *(uint2*)(ah + q * 4) = pack4(src[q]);
        }
    }
}

// ---------------------------------------------------------------------------
// Kernel 2: HMMA fp16 single-pass GEMM (R11 config — measured 13.3us).
//   C[512,1024] = A_f16[512,1152] @ W_f16[1024,1152]^T
// CTA tile 32(M)x64(N), 256 threads = 8 warps (2m x 4n, warp tile 16x16).
// GBK=64, 4-stage cp.async; 2 smem planes/stage (A, B). 55KB smem.
// ---------------------------------------------------------------------------
#define GBM 32
#define GBN 64
#define GBK 64
#define NSTAGE (DK_ / GBK)    // 18
#define STAGES 4
#define PADK 72               // 144B rows, ldmatrix conflict-free
#define A_PLANE (32 * PADK)               // 2304 elems
#define B_PLANE (64 * PADK)               // 4608 elems
#define STAGE_ELEMS (A_PLANE + B_PLANE)   // 6912 elems = 13824 B
#define OFF_AH 0
#define OFF_BH A_PLANE
#define SMEM_BYTES (STAGES * STAGE_ELEMS * 2)     // 55296

__global__ __launch_bounds__(256)
void gemm_hmma_kernel(const float* __restrict__ bias,
                      const float* __restrict__ time_table,
                      float* __restrict__ out) {
    extern __shared__ __half smem[];
    const uint32_t sbase = (uint32_t)__cvta_generic_to_shared(smem);

    const int tid = threadIdx.x;
    const int lane = tid & 31;
    const int warp = tid >> 5;              // 0..7
    const int warp_m = (warp & 1) * 16;     // 0 or 16
    const int warp_n = (warp >> 1) * 16;    // 0,16,32,48
    const int bm = blockIdx.y * GBM;
    const int bn = blockIdx.x * GBN;

    const int lrow = tid >> 3;              // 0..31
    const int lcq  = tid & 7;               // 0..7 (16B chunks of 128B)

    auto load_stage = [&](int st, int buf) {
        const long k0 = (long)st * GBK;
        const uint32_t sb0 = sbase + (uint32_t)(buf * STAGE_ELEMS) * 2;
        {
            const long aoff = (long)(bm + lrow) * DK_ + k0 + lcq * 8;
            const uint32_t soff = (uint32_t)(lrow * PADK + lcq * 8);
            cp16(sb0 + (OFF_AH + soff) * 2, g_Ah + aoff);
        }
#pragma unroll
        for (int h = 0; h < 2; ++h) {
            const int row = lrow + h * 32;
            const long boff = (long)(bn + row) * DK_ + k0 + lcq * 8;
            const uint32_t soff = (uint32_t)(row * PADK + lcq * 8);
            cp16(sb0 + (OFF_BH + soff) * 2, g_Wh + boff);
        }
        CP_COMMIT();
    };

    // ldmatrix lane mapping
    const int r8 = lane & 7;
    const int quad = lane >> 3;
    const int lm = (quad & 1) * 8 + r8;
    const int lk = (quad >> 1) * 8;

    float acc[2][4];
#pragma unroll
    for (int j = 0; j < 2; ++j)
#pragma unroll
        for (int q = 0; q < 4; ++q) acc[j][q] = 0.f;

    load_stage(0, 0);
    load_stage(1, 1);
    load_stage(2, 2);

    for (int st = 0; st < NSTAGE; ++st) {
        if (st < NSTAGE - 2)       { CP_WAIT(2); }
        else if (st == NSTAGE - 2) { CP_WAIT(1); }
        else                       { CP_WAIT(0); }
        __syncthreads();
        if (st + 3 < NSTAGE) load_stage(st + 3, (st + 3) & 3);

        const uint32_t sb0 = sbase + (uint32_t)((st & 3) * STAGE_ELEMS) * 2;
        const uint32_t abase = sb0 + OFF_AH * 2;
        const uint32_t bbase = sb0 + OFF_BH * 2;

#pragma unroll
        for (int ks = 0; ks < 4; ++ks) {
            const int kb = ks * 16;
            uint32_t ah[4], bh[4];
            const uint32_t ra = (uint32_t)((warp_m + lm) * PADK + kb + lk) * 2;
            const uint32_t rb = (uint32_t)((warp_n + lm) * PADK + kb + lk) * 2;
            ldmx4(ah, abase + ra);
            ldmx4(bh, bbase + rb);

            uint32_t bh0[2] = {bh[0], bh[2]}, bh1[2] = {bh[1], bh[3]};

            mma_f16(acc[0], ah, bh0);
            mma_f16(acc[1], ah, bh1);
        }
    }

    // ---- epilogue: + bias + time_table[clip(chosen,0,511)], * valid ----
    const int r = lane >> 2;
    const int kq = (lane & 3) * 2;
#pragma unroll
    for (int half = 0; half < 2; ++half) {
        const int m = bm + warp_m + r + half * 8;
        int tt = g_chosen[m];
        tt = tt < 0 ? 0 : (tt > 511 ? 511 : tt);
        const float vf = (float)g_valid[m];
        const float* te = time_table + (long)tt * D_;
        float* op = out + OFF_ENTRIES + (long)m * D_;
#pragma unroll
        for (int nt = 0; nt < 2; ++nt) {
            const int n0 = bn + warp_n + nt * 8 + kq;
            const float c0 = acc[nt][half * 2 + 0];
            const float c1 = acc[nt][half * 2 + 1];
            float2 o;
            o.x = (c0 + bias[n0]     + te[n0])     * vf;
            o.y = (c1 + bias[n0 + 1] + te[n0 + 1]) * vf;
            *(float2*)(op + n0) = o;
        }
    }
}

// ---------------------------------------------------------------------------
// Launch. Inputs: state_seq, holder_logits, event_scores, W, b, time_table
// ---------------------------------------------------------------------------
extern "C" void kernel_launch(void* const* d_in, const int* in_sizes, int n_in,
                              void* d_out, int out_size) {
    const float* state  = (const float*)d_in[0];
    const float* hl     = (const float*)d_in[1];
    const float* scores = (const float*)d_in[2];
    const float* W      = (const float*)d_in[3];
    const float* bias   = (const float*)d_in[4];
    const float* ttab   = (const float*)d_in[5];
    float* out = (float*)d_out;

    cudaFuncSetAttribute(gemm_hmma_kernel,
                         cudaFuncAttributeMaxDynamicSharedMemorySize,
                         SMEM_BYTES);

    prep_kernel<<<PREP_GRID, 512>>>(scores, state, hl, W, out, out_size);
    dim3 grid(D_ / GBN, M_ / GBM);   // (16, 16) = 256 CTAs
    gemm_hmma_kernel<<<grid, 256, SMEM_BYTES>>>(bias, ttab, out);
}